// round 12
// baseline (speedup 1.0000x reference)
#include <cuda_runtime.h>
#include <cuda_fp16.h>
#include <cstdint>
#include <cstddef>

// Problem dims
#define Bn 4096
#define Dn 256
#define Hn 2048
#define On 256

static constexpr size_t BH      = (size_t)Bn * Hn;
static constexpr size_t SE2_OFF = (size_t)8 * Bn * On;
static constexpr size_t SE3_OFF = SE2_OFF + (size_t)4 * BH;

// Scratch (.bss — no allocation)
__device__ __half g_h16[(size_t)18 * BH];      // fp16 hidden for all 18 experts
__device__ float g_gate[18 * Bn];
__device__ __half g_x16[(size_t)8 * Bn * Dn];  // fp16 copy of inputs

// Transposed fp16 weights: [N,K] K-major rows
static constexpr size_t WT_TASK = 0;                                   // 8  x [2048 x 256]
static constexpr size_t WT_B2   = (size_t)8 * 2048 * 256;              // 4  x [2048 x 512]
static constexpr size_t WT_B3   = WT_B2 + (size_t)4 * 2048 * 512;      // 6  x [2048 x 768]
static constexpr size_t WOT     = WT_B3 + (size_t)6 * 2048 * 768;      // 18 x [256 x 2048]
__device__ __half g_wt[WOT + (size_t)18 * 256 * 2048];

// Routing
__constant__ int c_cnt[8]    = {1, 3, 2, 2, 4, 2, 2, 2};
__constant__ int c_lst[8][4] = {
    {0,0,0,0},{1,8,9,0},{2,10,0,0},{3,11,0,0},
    {4,12,13,14},{5,15,0,0},{6,16,0,0},{7,17,0,0}
};
__constant__ int c_order[8] = {4, 1, 2, 3, 5, 6, 7, 0};  // heavy tasks first

// Prep-kernel segment tables (6 transpose segments)
__constant__ int c_segend[6] = {4096, 8192, 17408, 21504, 23552, 26624};
__constant__ int c_R[6] = {256, 512, 768, 2048, 2048, 2048};
__constant__ int c_C[6] = {2048, 2048, 2048, 256, 256, 256};
static constexpr int TR_TOTAL = 26624;
static constexpr int X16_BLOCKS = (int)(((size_t)8 * Bn * Dn / 4) / 256);  // 8192

struct P {
    const float* x[8];
    const float* W_task; const float* b_task; const float* Wg_task; const float* bg_task;
    const float* Wo_task; const float* bo_task;
    const float* W_b2;  const float* b_b2;  const float* Wg_b2;  const float* bg_b2;
    const float* Wo_b2; const float* bo_b2;
    const float* W_b3;  const float* b_b3;  const float* Wg_b3;  const float* bg_b3;
    const float* Wo_b3; const float* bo_b3;
    float* out;
};

// ===================== helpers =====================
__device__ __forceinline__ uint32_t smem_u32(const void* p) {
    uint32_t a;
    asm("{ .reg .u64 t; cvta.to.shared.u64 t, %1; cvt.u32.u64 %0, t; }" : "=r"(a) : "l"(p));
    return a;
}
__device__ __forceinline__ uint32_t pack2(float a, float b) {
    __half2 h = __floats2half2_rn(a, b);
    return *(uint32_t*)&h;
}
#define CP_ASYNC16(dst_u32, src_gptr) \
    asm volatile("cp.async.cg.shared.global [%0], [%1], 16;" :: "r"(dst_u32), "l"(src_gptr))
#define CP_COMMIT() asm volatile("cp.async.commit_group;" ::: "memory")
#define CP_WAIT0()  asm volatile("cp.async.wait_group 0;"  ::: "memory")
#define CP_WAIT1()  asm volatile("cp.async.wait_group 1;"  ::: "memory")

#define LDSM4(r0, r1, r2, r3, addr) \
    asm volatile("ldmatrix.sync.aligned.m8n8.x4.shared.b16 {%0,%1,%2,%3}, [%4];" \
                 : "=r"(r0), "=r"(r1), "=r"(r2), "=r"(r3) : "r"(addr))

#define MMA16(d, a, b) \
    asm volatile("mma.sync.aligned.m16n8k16.row.col.f32.f16.f16.f32 " \
                 "{%0,%1,%2,%3}, {%4,%5,%6,%7}, {%8,%9}, {%0,%1,%2,%3};" \
                 : "+f"((d)[0]), "+f"((d)[1]), "+f"((d)[2]), "+f"((d)[3]) \
                 : "r"((a)[0]), "r"((a)[1]), "r"((a)[2]), "r"((a)[3]), \
                   "r"((b)[0]), "r"((b)[1]))

// Smem tiles: 32 k-cols padded to 40 halves per row → conflict-free ldmatrix
#define TST 40
#define BUF (128 * TST)   // halves per buffer

// ===================== Kernel 0: fused prep (6 transposes + x fp16 copy) =====================
__global__ __launch_bounds__(256) void k_prep(P p) {
    const int bid = blockIdx.x;
    if (bid >= TR_TOTAL) {
        const size_t i = ((size_t)(bid - TR_TOTAL) * 256 + threadIdx.x) * 4;
        const size_t per = (size_t)Bn * Dn;
        const int e = (int)(i / per);
        const size_t off = i % per;
        const float4 v = *(const float4*)(p.x[e] + off);
        uint2 w;
        w.x = pack2(v.x, v.y);
        w.y = pack2(v.z, v.w);
        *(uint2*)(g_x16 + i) = w;
        return;
    }
    int s = 0;
#pragma unroll
    for (int i = 0; i < 6; i++) if (bid >= c_segend[i]) s = i + 1;
    const int local = bid - (s ? c_segend[s - 1] : 0);
    const int R = c_R[s], C = c_C[s];
    const int bx = C / 32, bpz = bx * (R / 32);
    const int z = local / bpz;
    const int rem = local - z * bpz;
    const int cb = (rem % bx) * 32, rb = (rem / bx) * 32;

    const float* inp;
    size_t off;
    switch (s) {
        case 0: inp = p.W_task;  off = WT_TASK; break;
        case 1: inp = p.W_b2;    off = WT_B2;   break;
        case 2: inp = p.W_b3;    off = WT_B3;   break;
        case 3: inp = p.Wo_task; off = WOT;     break;
        case 4: inp = p.Wo_b2;   off = WOT + (size_t)8  * 256 * 2048; break;
        default:inp = p.Wo_b3;   off = WOT + (size_t)12 * 256 * 2048; break;
    }
    const float* inz = inp + (size_t)z * R * C;
    __half* outz = g_wt + off + (size_t)z * R * C;

    __shared__ float tile[32][33];
    const int tx = threadIdx.x & 31, ty = threadIdx.x >> 5;
#pragma unroll
    for (int i = ty; i < 32; i += 8)
        tile[i][tx] = inz[(size_t)(rb + i) * C + cb + tx];
    __syncthreads();
#pragma unroll
    for (int i = ty; i < 32; i += 8)
        outz[(size_t)(cb + i) * R + rb + tx] = __float2half_rn(tile[tx][i]);
}

// ===================== Kernel 1: hidden = relu(X_e @ W_e + b_e) =====================
// grid (Hn/128, Bn/128, 18), 128 threads; CTA 128x128x32, warp 64x64 (2x2), occ 2,
// 3-stage cp.async pipeline.
__global__ __launch_bounds__(128, 2) void k_hidden_mma(P p) {
    extern __shared__ __half sm[];
    __half* As[3] = { sm,           sm + BUF,     sm + 2 * BUF };
    __half* Bs[3] = { sm + 3 * BUF, sm + 4 * BUF, sm + 5 * BUF };

    const int tid = threadIdx.x, wid = tid >> 5, lane = tid & 31;
    const int warp_m = wid >> 1, warp_n = wid & 1;
    const int g = lane >> 2, t = lane & 3;
    const int e = blockIdx.z;
    const int row0 = blockIdx.y * 128, n0 = blockIdx.x * 128;

    const __half *xp0, *xp1 = nullptr, *xp2 = nullptr;
    const float* bias;
    const __half* wt; int K; float* dst32 = nullptr;
    if (e < 8) {
        K = 256; xp0 = g_x16 + (size_t)e * Bn * Dn;
        wt = g_wt + WT_TASK + (size_t)e * Hn * 256;
        bias = p.b_task + e * Hn;
    } else if (e < 12) {
        const int q = e - 8;
        K = 512;
        xp0 = g_x16 + (size_t)2 * Bn * Dn; xp1 = g_x16 + (size_t)3 * Bn * Dn;
        wt = g_wt + WT_B2 + (size_t)q * Hn * 512;
        bias = p.b_b2 + q * Hn;
        dst32 = p.out + SE2_OFF + (size_t)q * BH;
    } else {
        const int q = e - 12;
        K = 768;
        xp0 = g_x16 + (size_t)5 * Bn * Dn; xp1 = g_x16 + (size_t)6 * Bn * Dn;
        xp2 = g_x16 + (size_t)7 * Bn * Dn;
        wt = g_wt + WT_B3 + (size_t)q * Hn * 768;
        bias = p.b_b3 + q * Hn;
        dst32 = p.out + SE3_OFF + (size_t)q * BH;
    }
    __half* dst16 = g_h16 + (size_t)e * BH;

    float acc[4][8][4];
#pragma unroll
    for (int m = 0; m < 4; m++)
#pragma unroll
        for (int n = 0; n < 8; n++)
#pragma unroll
            for (int r = 0; r < 4; r++) acc[m][n][r] = 0.f;

    auto STAGE = [&](int kc, int s) {
        const int kcol = kc * 32;
        const int part = kcol >> 8, kloc = kcol & 255;
        const __half* xa = (part == 0) ? xp0 : ((part == 1) ? xp1 : xp2);
        const uint32_t ab = smem_u32(As[s]);
        const uint32_t bb = smem_u32(Bs[s]);
#pragma unroll
        for (int it = 0; it < 4; it++) {
            const int item = tid + it * 128;
            const int r = item >> 2, cg = item & 3;
            CP_ASYNC16(ab + (r * TST + cg * 8) * 2, xa + (size_t)(row0 + r) * Dn + kloc + cg * 8);
            CP_ASYNC16(bb + (r * TST + cg * 8) * 2, wt + (size_t)(n0 + r) * K + kcol + cg * 8);
        }
        CP_COMMIT();
    };
    auto COMPUTE = [&](int s) {
        const uint32_t ab = smem_u32(As[s]);
        const uint32_t bb = smem_u32(Bs[s]);
#pragma unroll
        for (int kt = 0; kt < 2; kt++) {
            uint32_t af[4][4], bf[8][2];
#pragma unroll
            for (int m = 0; m < 4; m++) {
                const uint32_t addr = ab + (((warp_m * 64 + m * 16 + (lane & 15)) * TST)
                                            + kt * 16 + (lane >> 4) * 8) * 2;
                LDSM4(af[m][0], af[m][1], af[m][2], af[m][3], addr);
            }
#pragma unroll
            for (int nb = 0; nb < 4; nb++) {
                uint32_t r0, r1, r2, r3;
                const uint32_t addr = bb + (((warp_n * 64 + nb * 16 + (lane & 7) + ((lane >> 3) & 1) * 8) * TST)
                                            + kt * 16 + (lane >> 4) * 8) * 2;
                LDSM4(r0, r1, r2, r3, addr);
                bf[nb * 2][0] = r0;     bf[nb * 2][1] = r2;
                bf[nb * 2 + 1][0] = r1; bf[nb * 2 + 1][1] = r3;
            }
#pragma unroll
            for (int m = 0; m < 4; m++)
#pragma unroll
                for (int n = 0; n < 8; n++) MMA16(acc[m][n], af[m], bf[n]);
        }
    };

    const int KC = K / 32;
    STAGE(0, 0);
    STAGE(1, 1);
    CP_WAIT1();
    __syncthreads();
    int s = 0;
    for (int kc = 0; kc < KC; kc++, s = (s == 2) ? 0 : s + 1) {
        const bool more2 = (kc + 2 < KC);
        if (more2) {
            const int s2 = (s + 2 > 2) ? s - 1 : s + 2;
            STAGE(kc + 2, s2);
        }
        COMPUTE(s);
        if (kc + 1 < KC) {
            if (more2) CP_WAIT1(); else CP_WAIT0();
            __syncthreads();
        }
    }

#pragma unroll
    for (int m = 0; m < 4; m++) {
        const int row = row0 + warp_m * 64 + m * 16 + g;
#pragma unroll
        for (int n = 0; n < 8; n++) {
            const int col = n0 + warp_n * 64 + n * 8 + 2 * t;
            const float b0 = bias[col], b1 = bias[col + 1];
            float v0 = fmaxf(acc[m][n][0] + b0, 0.f);
            float v1 = fmaxf(acc[m][n][1] + b1, 0.f);
            float v2 = fmaxf(acc[m][n][2] + b0, 0.f);
            float v3 = fmaxf(acc[m][n][3] + b1, 0.f);
            *(uint32_t*)(dst16 + (size_t)row * Hn + col) = pack2(v0, v1);
            *(uint32_t*)(dst16 + (size_t)(row + 8) * Hn + col) = pack2(v2, v3);
            if (dst32) {
                *(float2*)(dst32 + (size_t)row * Hn + col) = make_float2(v0, v1);
                *(float2*)(dst32 + (size_t)(row + 8) * Hn + col) = make_float2(v2, v3);
            }
        }
    }
}

// ===================== Kernel 2: gates — one warp per (expert,row) =====================
__global__ __launch_bounds__(256) void k_gate(P p) {
    const int gw = blockIdx.x * 8 + (threadIdx.x >> 5);
    const int lane = threadIdx.x & 31;
    const int e = gw >> 12, row = gw & (Bn - 1);

    float s = 0.f;
    float bg;
    if (e < 8) {
        const float* src = p.x[e] + (size_t)row * Dn;
        const float* wg = p.Wg_task + e * Dn;
        bg = p.bg_task[e];
        for (int i = lane * 4; i < Dn; i += 128) {
            const float4 v = *(const float4*)(src + i);
            const float4 w = *(const float4*)(wg + i);
            s += v.x * w.x + v.y * w.y + v.z * w.z + v.w * w.w;
        }
    } else {
        const __half* src = g_h16 + (size_t)e * BH + (size_t)row * Hn;
        const float* wg;
        if (e < 12) { wg = p.Wg_b2 + (e - 8) * Hn;  bg = p.bg_b2[e - 8]; }
        else        { wg = p.Wg_b3 + (e - 12) * Hn; bg = p.bg_b3[e - 12]; }
        for (int i = lane * 8; i < Hn; i += 256) {
            const uint4 hv = *(const uint4*)(src + i);
            const __half2* hp = (const __half2*)&hv;
            const float4 w0 = *(const float4*)(wg + i);
            const float4 w1 = *(const float4*)(wg + i + 4);
            float2 f;
            f = __half22float2(hp[0]); s += f.x * w0.x + f.y * w0.y;
            f = __half22float2(hp[1]); s += f.x * w0.z + f.y * w0.w;
            f = __half22float2(hp[2]); s += f.x * w1.x + f.y * w1.y;
            f = __half22float2(hp[3]); s += f.x * w1.z + f.y * w1.w;
        }
    }
#pragma unroll
    for (int o = 16; o > 0; o >>= 1) s += __shfl_xor_sync(0xFFFFFFFFu, s, o);
    if (lane == 0)
        g_gate[e * Bn + row] = 1.f / (1.f + expf(-(s + bg)));
}

// ===================== Kernel 3: task_out, routed accumulation =====================
// grid (Bn/128, 8), 128 threads; CTA 128x256x32... actually 128x128 in N via 2 n-blocks?
// Keep R10 shape that measured best context: full N=256? No — use 128x128 CTA like R11
// but with 3-stage pipeline: grid (On/128, Bn/128, 8), 128 threads, warp 64x64 (2x2).
__global__ __launch_bounds__(128, 2) void k_out_mma(P p) {
    extern __shared__ __half sm[];
    __half* As[3] = { sm,           sm + BUF,     sm + 2 * BUF };
    __half* Bs[3] = { sm + 3 * BUF, sm + 4 * BUF, sm + 5 * BUF };
    __shared__ float gs[4][128];
    __shared__ float bsum[128];

    const int tid = threadIdx.x, wid = tid >> 5, lane = tid & 31;
    const int warp_m = wid >> 1, warp_n = wid & 1;
    const int g = lane >> 2, t = lane & 3;
    const int tk = c_order[blockIdx.z];
    const int row0 = blockIdx.y * 128, n0 = blockIdx.x * 128;
    const int nc = c_cnt[tk];

    const __half* hid[4]; const __half* wb[4];
    for (int ci = 0; ci < nc; ci++) {
        const int e = c_lst[tk][ci];
        hid[ci] = g_h16 + (size_t)e * BH;
        wb[ci] = g_wt + WOT + (size_t)e * On * Hn;
    }
    {
        float s = 0.f;
        for (int ci = 0; ci < nc; ci++) {
            const int e = c_lst[tk][ci];
            gs[ci][tid] = g_gate[e * Bn + row0 + tid];
            const float* bo = (e < 8) ? (p.bo_task + e * On)
                             : (e < 12) ? (p.bo_b2 + (e - 8) * On)
                                        : (p.bo_b3 + (e - 12) * On);
            s += bo[n0 + tid];
        }
        bsum[tid] = s;
    }
    __syncthreads();

    float acc[4][8][4];
#pragma unroll
    for (int m = 0; m < 4; m++)
#pragma unroll
        for (int n = 0; n < 8; n++)
#pragma unroll
            for (int r = 0; r < 4; r++) acc[m][n][r] = 0.f;

    const int arow = tid >> 2, acg = tid & 3;   // A staging: 4 rows x 1 col-group each
    uint4 pa[2][4];                              // 2-deep register prefetch
    auto LDGA = [&](int kc, int slot) {
        const int ci = kc >> 6, kcol = (kc & 63) * 32;
#pragma unroll
        for (int i = 0; i < 4; i++)
            pa[slot][i] = *(const uint4*)(hid[ci] + (size_t)(row0 + arow + i * 32) * Hn + kcol + acg * 8);
    };
    auto STSA = [&](int kc, int slot, int s) {
        const int ci = kc >> 6;
        __half* ab = As[s];
#pragma unroll
        for (int i = 0; i < 4; i++) {
            const float gv = gs[ci][arow + i * 32];
            const __half2* hp = (const __half2*)&pa[slot][i];
            uint4 w;
            uint32_t* wp = (uint32_t*)&w;
#pragma unroll
            for (int j = 0; j < 4; j++) {
                float2 f = __half22float2(hp[j]);
                wp[j] = pack2(f.x * gv, f.y * gv);
            }
            *(uint4*)(ab + (arow + i * 32) * TST + acg * 8) = w;
        }
    };
    auto CPB = [&](int kc, int s) {
        const int ci = kc >> 6, kcol = (kc & 63) * 32;
        const uint32_t bb = smem_u32(Bs[s]);
#pragma unroll
        for (int it = 0; it < 4; it++) {
            const int item = tid + it * 128;
            const int r = item >> 2, cg = item & 3;
            CP_ASYNC16(bb + (r * TST + cg * 8) * 2, wb[ci] + (size_t)(n0 + r) * Hn + kcol + cg * 8);
        }
        CP_COMMIT();
    };
    auto COMPUTE = [&](int s) {
        const uint32_t ab = smem_u32(As[s]);
        const uint32_t bb = smem_u32(Bs[s]);
#pragma unroll
        for (int kt = 0; kt < 2; kt++) {
            uint32_t af[4][4], bf[8][2];
#pragma unroll
            for (int m = 0; m < 4; m++) {
                const uint32_t addr = ab + (((warp_m * 64 + m * 16 + (lane & 15)) * TST)
                                            + kt * 16 + (lane >> 4) * 8) * 2;
                LDSM4(af[m][0], af[m][1], af[m][2], af[m][3], addr);
            }
#pragma unroll
            for (int nb = 0; nb < 4; nb++) {
                uint32_t r0, r1, r2, r3;
                const uint32_t addr = bb + (((warp_n * 64 + nb * 16 + (lane & 7) + ((lane >> 3) & 1) * 8) * TST)
                                            + kt * 16 + (lane >> 4) * 8) * 2;
                LDSM4(r0, r1, r2, r3, addr);
                bf[nb * 2][0] = r0;     bf[nb * 2][1] = r2;
                bf[nb * 2 + 1][0] = r1; bf[nb * 2 + 1][1] = r3;
            }
#pragma unroll
            for (int m = 0; m < 4; m++)
#pragma unroll
                for (int n = 0; n < 8; n++) MMA16(acc[m][n], af[m], bf[n]);
        }
    };

    const int KC = nc * 64;
    // prologue: A0 direct, A1 in slot1; B stages 0,1
    LDGA(0, 0); STSA(0, 0, 0);
    LDGA(1, 1);
    CPB(0, 0);
    CPB(1, 1);
    CP_WAIT1();
    __syncthreads();   // buf0 (A+B) visible
    // pre-store A1 into buffer 1 (buffer 1 is free — nothing computed yet)
    STSA(1, 1, 1);
    __syncthreads();

    int s = 0;
    for (int kc = 0; kc < KC; kc++, s = (s == 2) ? 0 : s + 1) {
        const bool more2 = (kc + 2 < KC);
        if (more2) {
            const int s2 = (s + 2 > 2) ? s - 1 : s + 2;
            CPB(kc + 2, s2);
            LDGA(kc + 2, kc & 1);   // slot (kc+2)%2 == kc%2
        }
        COMPUTE(s);
        if (kc + 1 < KC) {
            if (more2) {
                const int s2 = (s + 2 > 2) ? s - 1 : s + 2;
                STSA(kc + 2, kc & 1, s2);   // A for kc+2 into its buffer
                CP_WAIT1();
            } else {
                CP_WAIT0();
            }
            __syncthreads();
        }
    }

    float* outt = p.out + (size_t)tk * Bn * On;
#pragma unroll
    for (int m = 0; m < 4; m++) {
        const int row = row0 + warp_m * 64 + m * 16 + g;
#pragma unroll
        for (int n = 0; n < 8; n++) {
            const int cl = warp_n * 64 + n * 8 + 2 * t;
            const float b0 = bsum[cl], b1 = bsum[cl + 1];
            float2 v;
            v.x = acc[m][n][0] + b0;
            v.y = acc[m][n][1] + b1;
            *(float2*)(outt + (size_t)row * On + n0 + cl) = v;
            v.x = acc[m][n][2] + b0;
            v.y = acc[m][n][3] + b1;
            *(float2*)(outt + (size_t)(row + 8) * On + n0 + cl) = v;
        }
    }
}

// ===================== Host launch =====================
extern "C" void kernel_launch(void* const* d_in, const int* in_sizes, int n_in,
                              void* d_out, int out_size) {
    P p;
    for (int i = 0; i < 8; i++) p.x[i] = (const float*)d_in[i];
    p.W_task  = (const float*)d_in[8];
    p.b_task  = (const float*)d_in[9];
    p.Wg_task = (const float*)d_in[10];
    p.bg_task = (const float*)d_in[11];
    p.Wo_task = (const float*)d_in[12];
    p.bo_task = (const float*)d_in[13];
    p.W_b2    = (const float*)d_in[14];
    p.b_b2    = (const float*)d_in[15];
    p.Wg_b2   = (const float*)d_in[16];
    p.bg_b2   = (const float*)d_in[17];
    p.Wo_b2   = (const float*)d_in[18];
    p.bo_b2   = (const float*)d_in[19];
    p.W_b3    = (const float*)d_in[20];
    p.b_b3    = (const float*)d_in[21];
    p.Wg_b3   = (const float*)d_in[22];
    p.bg_b3   = (const float*)d_in[23];
    p.Wo_b3   = (const float*)d_in[24];
    p.bo_b3   = (const float*)d_in[25];
    p.out = (float*)d_out;

    const int smg = 6 * BUF * 2;   // 61440 B (3-stage, occ 2)
    cudaFuncSetAttribute(k_hidden_mma, cudaFuncAttributeMaxDynamicSharedMemorySize, smg);
    cudaFuncSetAttribute(k_out_mma,    cudaFuncAttributeMaxDynamicSharedMemorySize, smg);

    k_prep<<<TR_TOTAL + X16_BLOCKS, 256>>>(p);
    k_hidden_mma<<<dim3(Hn / 128, Bn / 128, 18), 128, smg>>>(p);
    k_gate<<<dim3(18 * Bn / 8), 256>>>(p);
    k_out_mma<<<dim3(On / 128, Bn / 128, 8), 128, smg>>>(p);
}

// round 13
// speedup vs baseline: 1.3970x; 1.3970x over previous
#include <cuda_runtime.h>
#include <cuda_fp16.h>
#include <cstdint>
#include <cstddef>

// Problem dims
#define Bn 4096
#define Dn 256
#define Hn 2048
#define On 256

static constexpr size_t BH      = (size_t)Bn * Hn;
static constexpr size_t SE2_OFF = (size_t)8 * Bn * On;
static constexpr size_t SE3_OFF = SE2_OFF + (size_t)4 * BH;

// Scratch (.bss — no allocation)
__device__ __half g_h16[(size_t)18 * BH];      // fp16 hidden for all 18 experts
__device__ float g_gate[18 * Bn];
__device__ __half g_x16[(size_t)8 * Bn * Dn];  // fp16 copy of inputs

// Transposed fp16 weights: [N,K] K-major rows
static constexpr size_t WT_TASK = 0;                                   // 8  x [2048 x 256]
static constexpr size_t WT_B2   = (size_t)8 * 2048 * 256;              // 4  x [2048 x 512]
static constexpr size_t WT_B3   = WT_B2 + (size_t)4 * 2048 * 512;      // 6  x [2048 x 768]
static constexpr size_t WOT     = WT_B3 + (size_t)6 * 2048 * 768;      // 18 x [256 x 2048]
__device__ __half g_wt[WOT + (size_t)18 * 256 * 2048];

// Routing
__constant__ int c_cnt[8]    = {1, 3, 2, 2, 4, 2, 2, 2};
__constant__ int c_lst[8][4] = {
    {0,0,0,0},{1,8,9,0},{2,10,0,0},{3,11,0,0},
    {4,12,13,14},{5,15,0,0},{6,16,0,0},{7,17,0,0}
};
__constant__ int c_order[8] = {4, 1, 2, 3, 5, 6, 7, 0};  // heavy tasks first

// Prep-kernel segment tables (6 transpose segments)
__constant__ int c_segend[6] = {4096, 8192, 17408, 21504, 23552, 26624};
__constant__ int c_R[6] = {256, 512, 768, 2048, 2048, 2048};
__constant__ int c_C[6] = {2048, 2048, 2048, 256, 256, 256};
static constexpr int TR_TOTAL = 26624;
static constexpr int X16_BLOCKS = (int)(((size_t)8 * Bn * Dn / 4) / 256);  // 8192

struct P {
    const float* x[8];
    const float* W_task; const float* b_task; const float* Wg_task; const float* bg_task;
    const float* Wo_task; const float* bo_task;
    const float* W_b2;  const float* b_b2;  const float* Wg_b2;  const float* bg_b2;
    const float* Wo_b2; const float* bo_b2;
    const float* W_b3;  const float* b_b3;  const float* Wg_b3;  const float* bg_b3;
    const float* Wo_b3; const float* bo_b3;
    float* out;
};

// ===================== helpers =====================
__device__ __forceinline__ uint32_t smem_u32(const void* p) {
    uint32_t a;
    asm("{ .reg .u64 t; cvta.to.shared.u64 t, %1; cvt.u32.u64 %0, t; }" : "=r"(a) : "l"(p));
    return a;
}
__device__ __forceinline__ uint32_t pack2(float a, float b) {
    __half2 h = __floats2half2_rn(a, b);
    return *(uint32_t*)&h;
}
#define CP_ASYNC16(dst_u32, src_gptr) \
    asm volatile("cp.async.cg.shared.global [%0], [%1], 16;" :: "r"(dst_u32), "l"(src_gptr))
#define CP_COMMIT() asm volatile("cp.async.commit_group;" ::: "memory")
#define CP_WAIT0()  asm volatile("cp.async.wait_group 0;"  ::: "memory")

#define LDSM4(r0, r1, r2, r3, addr) \
    asm volatile("ldmatrix.sync.aligned.m8n8.x4.shared.b16 {%0,%1,%2,%3}, [%4];" \
                 : "=r"(r0), "=r"(r1), "=r"(r2), "=r"(r3) : "r"(addr))

#define MMA16(d, a, b) \
    asm volatile("mma.sync.aligned.m16n8k16.row.col.f32.f16.f16.f32 " \
                 "{%0,%1,%2,%3}, {%4,%5,%6,%7}, {%8,%9}, {%0,%1,%2,%3};" \
                 : "+f"((d)[0]), "+f"((d)[1]), "+f"((d)[2]), "+f"((d)[3]) \
                 : "r"((a)[0]), "r"((a)[1]), "r"((a)[2]), "r"((a)[3]), \
                   "r"((b)[0]), "r"((b)[1]))

// Smem tiles: 32 k-cols padded to 40 halves per row → conflict-free ldmatrix
#define TST 40
#define BUF (128 * TST)

// ===================== Kernel 0: fused prep (6 transposes + x fp16 copy) =====================
__global__ __launch_bounds__(256) void k_prep(P p) {
    const int bid = blockIdx.x;
    if (bid >= TR_TOTAL) {
        const size_t i = ((size_t)(bid - TR_TOTAL) * 256 + threadIdx.x) * 4;
        const size_t per = (size_t)Bn * Dn;
        const int e = (int)(i / per);
        const size_t off = i % per;
        const float4 v = *(const float4*)(p.x[e] + off);
        uint2 w;
        w.x = pack2(v.x, v.y);
        w.y = pack2(v.z, v.w);
        *(uint2*)(g_x16 + i) = w;
        return;
    }
    int s = 0;
#pragma unroll
    for (int i = 0; i < 6; i++) if (bid >= c_segend[i]) s = i + 1;
    const int local = bid - (s ? c_segend[s - 1] : 0);
    const int R = c_R[s], C = c_C[s];
    const int bx = C / 32, bpz = bx * (R / 32);
    const int z = local / bpz;
    const int rem = local - z * bpz;
    const int cb = (rem % bx) * 32, rb = (rem / bx) * 32;

    const float* inp;
    size_t off;
    switch (s) {
        case 0: inp = p.W_task;  off = WT_TASK; break;
        case 1: inp = p.W_b2;    off = WT_B2;   break;
        case 2: inp = p.W_b3;    off = WT_B3;   break;
        case 3: inp = p.Wo_task; off = WOT;     break;
        case 4: inp = p.Wo_b2;   off = WOT + (size_t)8  * 256 * 2048; break;
        default:inp = p.Wo_b3;   off = WOT + (size_t)12 * 256 * 2048; break;
    }
    const float* inz = inp + (size_t)z * R * C;
    __half* outz = g_wt + off + (size_t)z * R * C;

    __shared__ float tile[32][33];
    const int tx = threadIdx.x & 31, ty = threadIdx.x >> 5;
#pragma unroll
    for (int i = ty; i < 32; i += 8)
        tile[i][tx] = inz[(size_t)(rb + i) * C + cb + tx];
    __syncthreads();
#pragma unroll
    for (int i = ty; i < 32; i += 8)
        outz[(size_t)(cb + i) * R + rb + tx] = __float2half_rn(tile[tx][i]);
}

// ===================== Kernel 1: hidden = relu(X_e @ W_e + b_e) =====================
// grid (Hn/128, Bn/128, 18), 256 threads; CTA 128x128x32, warp 64x32 (2x4), occ 2
// → 16 warps/SM. 2-stage cp.async pipeline, compile-time buffer indices.
__global__ __launch_bounds__(256, 2) void k_hidden_mma(P p) {
    extern __shared__ __half sm[];
    __half* As[2] = { sm,           sm + BUF };
    __half* Bs[2] = { sm + 2 * BUF, sm + 3 * BUF };

    const int tid = threadIdx.x, wid = tid >> 5, lane = tid & 31;
    const int warp_m = wid >> 2, warp_n = wid & 3;
    const int g = lane >> 2, t = lane & 3;
    const int e = blockIdx.z;
    const int row0 = blockIdx.y * 128, n0 = blockIdx.x * 128;

    const __half *xp0, *xp1 = nullptr, *xp2 = nullptr;
    const float* bias;
    const __half* wt; int K; float* dst32 = nullptr;
    if (e < 8) {
        K = 256; xp0 = g_x16 + (size_t)e * Bn * Dn;
        wt = g_wt + WT_TASK + (size_t)e * Hn * 256;
        bias = p.b_task + e * Hn;
    } else if (e < 12) {
        const int q = e - 8;
        K = 512;
        xp0 = g_x16 + (size_t)2 * Bn * Dn; xp1 = g_x16 + (size_t)3 * Bn * Dn;
        wt = g_wt + WT_B2 + (size_t)q * Hn * 512;
        bias = p.b_b2 + q * Hn;
        dst32 = p.out + SE2_OFF + (size_t)q * BH;
    } else {
        const int q = e - 12;
        K = 768;
        xp0 = g_x16 + (size_t)5 * Bn * Dn; xp1 = g_x16 + (size_t)6 * Bn * Dn;
        xp2 = g_x16 + (size_t)7 * Bn * Dn;
        wt = g_wt + WT_B3 + (size_t)q * Hn * 768;
        bias = p.b_b3 + q * Hn;
        dst32 = p.out + SE3_OFF + (size_t)q * BH;
    }
    __half* dst16 = g_h16 + (size_t)e * BH;

    float acc[4][4][4];
#pragma unroll
    for (int m = 0; m < 4; m++)
#pragma unroll
        for (int n = 0; n < 4; n++)
#pragma unroll
            for (int r = 0; r < 4; r++) acc[m][n][r] = 0.f;

    auto CPA = [&](int kc, int s) {
        const int kcol = kc * 32;
        const int part = kcol >> 8, kloc = kcol & 255;
        const __half* xa = (part == 0) ? xp0 : ((part == 1) ? xp1 : xp2);
        const uint32_t ab = smem_u32(As[s]);
#pragma unroll
        for (int it = 0; it < 2; it++) {
            const int item = tid + it * 256;
            const int r = item >> 2, cg = item & 3;
            CP_ASYNC16(ab + (r * TST + cg * 8) * 2, xa + (size_t)(row0 + r) * Dn + kloc + cg * 8);
        }
    };
    auto CPB = [&](int kc, int s) {
        const int kcol = kc * 32;
        const uint32_t bb = smem_u32(Bs[s]);
#pragma unroll
        for (int it = 0; it < 2; it++) {
            const int item = tid + it * 256;
            const int r = item >> 2, cg = item & 3;
            CP_ASYNC16(bb + (r * TST + cg * 8) * 2, wt + (size_t)(n0 + r) * K + kcol + cg * 8);
        }
    };
    auto COMPUTE = [&](int s) {
        const uint32_t ab = smem_u32(As[s]);
        const uint32_t bb = smem_u32(Bs[s]);
#pragma unroll
        for (int kt = 0; kt < 2; kt++) {
            uint32_t af[4][4], bf[4][2];
#pragma unroll
            for (int m = 0; m < 4; m++) {
                const uint32_t addr = ab + (((warp_m * 64 + m * 16 + (lane & 15)) * TST)
                                            + kt * 16 + (lane >> 4) * 8) * 2;
                LDSM4(af[m][0], af[m][1], af[m][2], af[m][3], addr);
            }
#pragma unroll
            for (int nb = 0; nb < 2; nb++) {
                uint32_t r0, r1, r2, r3;
                const uint32_t addr = bb + (((warp_n * 32 + nb * 16 + (lane & 7) + ((lane >> 3) & 1) * 8) * TST)
                                            + kt * 16 + (lane >> 4) * 8) * 2;
                LDSM4(r0, r1, r2, r3, addr);
                bf[nb * 2][0] = r0;     bf[nb * 2][1] = r2;
                bf[nb * 2 + 1][0] = r1; bf[nb * 2 + 1][1] = r3;
            }
#pragma unroll
            for (int m = 0; m < 4; m++)
#pragma unroll
                for (int n = 0; n < 4; n++) MMA16(acc[m][n], af[m], bf[n]);
        }
    };

    const int KC = K / 32;
    CPA(0, 0); CPB(0, 0); CP_COMMIT();
    CP_WAIT0();
    __syncthreads();
    for (int kc = 0; kc < KC; kc++) {
        const int s = kc & 1;
        const bool more = (kc + 1 < KC);
        if (more) { CPA(kc + 1, s ^ 1); CPB(kc + 1, s ^ 1); CP_COMMIT(); }
        COMPUTE(s);
        if (more) { CP_WAIT0(); __syncthreads(); }
    }

#pragma unroll
    for (int m = 0; m < 4; m++) {
        const int row = row0 + warp_m * 64 + m * 16 + g;
#pragma unroll
        for (int n = 0; n < 4; n++) {
            const int col = n0 + warp_n * 32 + n * 8 + 2 * t;
            const float b0 = bias[col], b1 = bias[col + 1];
            float v0 = fmaxf(acc[m][n][0] + b0, 0.f);
            float v1 = fmaxf(acc[m][n][1] + b1, 0.f);
            float v2 = fmaxf(acc[m][n][2] + b0, 0.f);
            float v3 = fmaxf(acc[m][n][3] + b1, 0.f);
            *(uint32_t*)(dst16 + (size_t)row * Hn + col) = pack2(v0, v1);
            *(uint32_t*)(dst16 + (size_t)(row + 8) * Hn + col) = pack2(v2, v3);
            if (dst32) {
                *(float2*)(dst32 + (size_t)row * Hn + col) = make_float2(v0, v1);
                *(float2*)(dst32 + (size_t)(row + 8) * Hn + col) = make_float2(v2, v3);
            }
        }
    }
}

// ===================== Kernel 2: gates — one warp per (expert,row) =====================
__global__ __launch_bounds__(256) void k_gate(P p) {
    const int gw = blockIdx.x * 8 + (threadIdx.x >> 5);
    const int lane = threadIdx.x & 31;
    const int e = gw >> 12, row = gw & (Bn - 1);

    float s = 0.f;
    float bg;
    if (e < 8) {
        const float* src = p.x[e] + (size_t)row * Dn;
        const float* wg = p.Wg_task + e * Dn;
        bg = p.bg_task[e];
        for (int i = lane * 4; i < Dn; i += 128) {
            const float4 v = *(const float4*)(src + i);
            const float4 w = *(const float4*)(wg + i);
            s += v.x * w.x + v.y * w.y + v.z * w.z + v.w * w.w;
        }
    } else {
        const __half* src = g_h16 + (size_t)e * BH + (size_t)row * Hn;
        const float* wg;
        if (e < 12) { wg = p.Wg_b2 + (e - 8) * Hn;  bg = p.bg_b2[e - 8]; }
        else        { wg = p.Wg_b3 + (e - 12) * Hn; bg = p.bg_b3[e - 12]; }
        for (int i = lane * 8; i < Hn; i += 256) {
            const uint4 hv = *(const uint4*)(src + i);
            const __half2* hp = (const __half2*)&hv;
            const float4 w0 = *(const float4*)(wg + i);
            const float4 w1 = *(const float4*)(wg + i + 4);
            float2 f;
            f = __half22float2(hp[0]); s += f.x * w0.x + f.y * w0.y;
            f = __half22float2(hp[1]); s += f.x * w0.z + f.y * w0.w;
            f = __half22float2(hp[2]); s += f.x * w1.x + f.y * w1.y;
            f = __half22float2(hp[3]); s += f.x * w1.z + f.y * w1.w;
        }
    }
#pragma unroll
    for (int o = 16; o > 0; o >>= 1) s += __shfl_xor_sync(0xFFFFFFFFu, s, o);
    if (lane == 0)
        g_gate[e * Bn + row] = 1.f / (1.f + expf(-(s + bg)));
}

// ===================== Kernel 3: task_out, routed accumulation =====================
// grid (On/128, Bn/128, 8), 256 threads; CTA 128x128x32, warp 64x32 (2x4), occ 2
// → 16 warps/SM. 2-stage pipeline, compile-time indices.
__global__ __launch_bounds__(256, 2) void k_out_mma(P p) {
    extern __shared__ __half sm[];
    __half* As[2] = { sm,           sm + BUF };
    __half* Bs[2] = { sm + 2 * BUF, sm + 3 * BUF };
    __shared__ float gs[4][128];
    __shared__ float bsum[128];

    const int tid = threadIdx.x, wid = tid >> 5, lane = tid & 31;
    const int warp_m = wid >> 2, warp_n = wid & 3;
    const int g = lane >> 2, t = lane & 3;
    const int tk = c_order[blockIdx.z];
    const int row0 = blockIdx.y * 128, n0 = blockIdx.x * 128;
    const int nc = c_cnt[tk];

    const __half* hid[4]; const __half* wb[4];
    for (int ci = 0; ci < nc; ci++) {
        const int e = c_lst[tk][ci];
        hid[ci] = g_h16 + (size_t)e * BH;
        wb[ci] = g_wt + WOT + (size_t)e * On * Hn;
    }
    {
        float s = 0.f;
        for (int ci = 0; ci < nc; ci++) {
            const int e = c_lst[tk][ci];
            if (tid < 128) gs[ci][tid] = g_gate[e * Bn + row0 + tid];
            const float* bo = (e < 8) ? (p.bo_task + e * On)
                             : (e < 12) ? (p.bo_b2 + (e - 8) * On)
                                        : (p.bo_b3 + (e - 12) * On);
            if (tid < 128) s += bo[n0 + tid];
        }
        if (tid < 128) bsum[tid] = s;
    }
    __syncthreads();

    float acc[4][4][4];
#pragma unroll
    for (int m = 0; m < 4; m++)
#pragma unroll
        for (int n = 0; n < 4; n++)
#pragma unroll
            for (int r = 0; r < 4; r++) acc[m][n][r] = 0.f;

    const int arow = tid >> 1, acg = (tid & 1) * 2;   // A staging: 1 row x 2 col-groups
    uint4 pa[2];
    auto LDGA = [&](int kc) {
        const int ci = kc >> 6, kcol = (kc & 63) * 32;
        const __half* rp = hid[ci] + (size_t)(row0 + arow) * Hn + kcol;
#pragma unroll
        for (int i = 0; i < 2; i++)
            pa[i] = *(const uint4*)(rp + (acg + i) * 8);
    };
    auto STSA = [&](int kc, int s) {
        const int ci = kc >> 6;
        const float gv = gs[ci][arow];
        __half* ab = As[s];
#pragma unroll
        for (int i = 0; i < 2; i++) {
            const __half2* hp = (const __half2*)&pa[i];
            uint4 w;
            uint32_t* wp = (uint32_t*)&w;
#pragma unroll
            for (int j = 0; j < 4; j++) {
                float2 f = __half22float2(hp[j]);
                wp[j] = pack2(f.x * gv, f.y * gv);
            }
            *(uint4*)(ab + arow * TST + (acg + i) * 8) = w;
        }
    };
    auto CPB = [&](int kc, int s) {
        const int ci = kc >> 6, kcol = (kc & 63) * 32;
        const uint32_t bb = smem_u32(Bs[s]);
#pragma unroll
        for (int it = 0; it < 2; it++) {
            const int item = tid + it * 256;         // 512 items: 128 rows x 4 col-groups
            const int r = item >> 2, cg = item & 3;
            CP_ASYNC16(bb + (r * TST + cg * 8) * 2, wb[ci] + (size_t)(n0 + r) * Hn + kcol + cg * 8);
        }
    };
    auto COMPUTE = [&](int s) {
        const uint32_t ab = smem_u32(As[s]);
        const uint32_t bb = smem_u32(Bs[s]);
#pragma unroll
        for (int kt = 0; kt < 2; kt++) {
            uint32_t af[4][4], bf[4][2];
#pragma unroll
            for (int m = 0; m < 4; m++) {
                const uint32_t addr = ab + (((warp_m * 64 + m * 16 + (lane & 15)) * TST)
                                            + kt * 16 + (lane >> 4) * 8) * 2;
                LDSM4(af[m][0], af[m][1], af[m][2], af[m][3], addr);
            }
#pragma unroll
            for (int nb = 0; nb < 2; nb++) {
                uint32_t r0, r1, r2, r3;
                const uint32_t addr = bb + (((warp_n * 32 + nb * 16 + (lane & 7) + ((lane >> 3) & 1) * 8) * TST)
                                            + kt * 16 + (lane >> 4) * 8) * 2;
                LDSM4(r0, r1, r2, r3, addr);
                bf[nb * 2][0] = r0;     bf[nb * 2][1] = r2;
                bf[nb * 2 + 1][0] = r1; bf[nb * 2 + 1][1] = r3;
            }
#pragma unroll
            for (int m = 0; m < 4; m++)
#pragma unroll
                for (int n = 0; n < 4; n++) MMA16(acc[m][n], af[m], bf[n]);
        }
    };

    const int KC = nc * 64;
    LDGA(0); CPB(0, 0); CP_COMMIT(); STSA(0, 0);
    CP_WAIT0();
    __syncthreads();
    for (int kc = 0; kc < KC; kc++) {
        const int s = kc & 1;
        const bool more = (kc + 1 < KC);
        if (more) { LDGA(kc + 1); CPB(kc + 1, s ^ 1); CP_COMMIT(); }
        COMPUTE(s);
        if (more) { STSA(kc + 1, s ^ 1); CP_WAIT0(); __syncthreads(); }
    }

    float* outt = p.out + (size_t)tk * Bn * On;
#pragma unroll
    for (int m = 0; m < 4; m++) {
        const int row = row0 + warp_m * 64 + m * 16 + g;
#pragma unroll
        for (int n = 0; n < 4; n++) {
            const int cl = warp_n * 32 + n * 8 + 2 * t;
            const float b0 = bsum[cl], b1 = bsum[cl + 1];
            float2 v;
            v.x = acc[m][n][0] + b0;
            v.y = acc[m][n][1] + b1;
            *(float2*)(outt + (size_t)row * On + n0 + cl) = v;
            v.x = acc[m][n][2] + b0;
            v.y = acc[m][n][3] + b1;
            *(float2*)(outt + (size_t)(row + 8) * On + n0 + cl) = v;
        }
    }
}

// ===================== Host launch =====================
extern "C" void kernel_launch(void* const* d_in, const int* in_sizes, int n_in,
                              void* d_out, int out_size) {
    P p;
    for (int i = 0; i < 8; i++) p.x[i] = (const float*)d_in[i];
    p.W_task  = (const float*)d_in[8];
    p.b_task  = (const float*)d_in[9];
    p.Wg_task = (const float*)d_in[10];
    p.bg_task = (const float*)d_in[11];
    p.Wo_task = (const float*)d_in[12];
    p.bo_task = (const float*)d_in[13];
    p.W_b2    = (const float*)d_in[14];
    p.b_b2    = (const float*)d_in[15];
    p.Wg_b2   = (const float*)d_in[16];
    p.bg_b2   = (const float*)d_in[17];
    p.Wo_b2   = (const float*)d_in[18];
    p.bo_b2   = (const float*)d_in[19];
    p.W_b3    = (const float*)d_in[20];
    p.b_b3    = (const float*)d_in[21];
    p.Wg_b3   = (const float*)d_in[22];
    p.bg_b3   = (const float*)d_in[23];
    p.Wo_b3   = (const float*)d_in[24];
    p.bo_b3   = (const float*)d_in[25];
    p.out = (float*)d_out;

    const int smg = 4 * BUF * 2;   // 40960 B (2-stage, occ 2)
    cudaFuncSetAttribute(k_hidden_mma, cudaFuncAttributeMaxDynamicSharedMemorySize, smg);
    cudaFuncSetAttribute(k_out_mma,    cudaFuncAttributeMaxDynamicSharedMemorySize, smg);

    k_prep<<<TR_TOTAL + X16_BLOCKS, 256>>>(p);
    k_hidden_mma<<<dim3(Hn / 128, Bn / 128, 18), 256, smg>>>(p);
    k_gate<<<dim3(18 * Bn / 8), 256>>>(p);
    k_out_mma<<<dim3(On / 128, Bn / 128, 8), 256, smg>>>(p);
}

// round 14
// speedup vs baseline: 1.5189x; 1.0872x over previous
#include <cuda_runtime.h>
#include <cuda_fp16.h>
#include <cstdint>
#include <cstddef>

// Problem dims
#define Bn 4096
#define Dn 256
#define Hn 2048
#define On 256

static constexpr size_t BH      = (size_t)Bn * Hn;
static constexpr size_t SE2_OFF = (size_t)8 * Bn * On;
static constexpr size_t SE3_OFF = SE2_OFF + (size_t)4 * BH;

// Scratch (.bss — no allocation)
__device__ __half g_h16[(size_t)18 * BH];      // fp16 hidden for all 18 experts
__device__ float g_gate[18 * Bn];
__device__ __half g_x16[(size_t)8 * Bn * Dn];  // fp16 copy of inputs

// Transposed fp16 weights: [N,K] K-major rows
static constexpr size_t WT_TASK = 0;                                   // 8  x [2048 x 256]
static constexpr size_t WT_B2   = (size_t)8 * 2048 * 256;              // 4  x [2048 x 512]
static constexpr size_t WT_B3   = WT_B2 + (size_t)4 * 2048 * 512;      // 6  x [2048 x 768]
static constexpr size_t WOT     = WT_B3 + (size_t)6 * 2048 * 768;      // 18 x [256 x 2048]
__device__ __half g_wt[WOT + (size_t)18 * 256 * 2048];

// Routing
__constant__ int c_cnt[8]    = {1, 3, 2, 2, 4, 2, 2, 2};
__constant__ int c_lst[8][4] = {
    {0,0,0,0},{1,8,9,0},{2,10,0,0},{3,11,0,0},
    {4,12,13,14},{5,15,0,0},{6,16,0,0},{7,17,0,0}
};
__constant__ int c_order[8] = {4, 1, 2, 3, 5, 6, 7, 0};  // heavy tasks first

// Prep-kernel segment tables (6 transpose segments)
__constant__ int c_segend[6] = {4096, 8192, 17408, 21504, 23552, 26624};
__constant__ int c_R[6] = {256, 512, 768, 2048, 2048, 2048};
__constant__ int c_C[6] = {2048, 2048, 2048, 256, 256, 256};
static constexpr int TR_TOTAL = 26624;
static constexpr int X16_BLOCKS = (int)(((size_t)8 * Bn * Dn / 4) / 256);  // 8192

struct P {
    const float* x[8];
    const float* W_task; const float* b_task; const float* Wg_task; const float* bg_task;
    const float* Wo_task; const float* bo_task;
    const float* W_b2;  const float* b_b2;  const float* Wg_b2;  const float* bg_b2;
    const float* Wo_b2; const float* bo_b2;
    const float* W_b3;  const float* b_b3;  const float* Wg_b3;  const float* bg_b3;
    const float* Wo_b3; const float* bo_b3;
    float* out;
};

// ===================== helpers =====================
__device__ __forceinline__ uint32_t smem_u32(const void* p) {
    uint32_t a;
    asm("{ .reg .u64 t; cvta.to.shared.u64 t, %1; cvt.u32.u64 %0, t; }" : "=r"(a) : "l"(p));
    return a;
}
__device__ __forceinline__ uint32_t pack2(float a, float b) {
    __half2 h = __floats2half2_rn(a, b);
    return *(uint32_t*)&h;
}
#define CP_ASYNC16(dst_u32, src_gptr) \
    asm volatile("cp.async.cg.shared.global [%0], [%1], 16;" :: "r"(dst_u32), "l"(src_gptr))
#define CP_COMMIT() asm volatile("cp.async.commit_group;" ::: "memory")
#define CP_WAIT0()  asm volatile("cp.async.wait_group 0;"  ::: "memory")

#define LDSM4(r0, r1, r2, r3, addr) \
    asm volatile("ldmatrix.sync.aligned.m8n8.x4.shared.b16 {%0,%1,%2,%3}, [%4];" \
                 : "=r"(r0), "=r"(r1), "=r"(r2), "=r"(r3) : "r"(addr))

#define MMA16(d, a, b) \
    asm volatile("mma.sync.aligned.m16n8k16.row.col.f32.f16.f16.f32 " \
                 "{%0,%1,%2,%3}, {%4,%5,%6,%7}, {%8,%9}, {%0,%1,%2,%3};" \
                 : "+f"((d)[0]), "+f"((d)[1]), "+f"((d)[2]), "+f"((d)[3]) \
                 : "r"((a)[0]), "r"((a)[1]), "r"((a)[2]), "r"((a)[3]), \
                   "r"((b)[0]), "r"((b)[1]))

// k_out smem tiles: 32 k-cols padded to 40 halves per row
#define TST 40
#define BUF (128 * TST)
// k_hidden smem tiles: 64 k-cols padded to 72 halves per row (144 B ≡ 16 mod 128 → conflict-free)
#define HTST 72
#define HBUF (128 * HTST)

// ===================== Kernel 0: fused prep (6 transposes + x fp16 copy) =====================
__global__ __launch_bounds__(256) void k_prep(P p) {
    const int bid = blockIdx.x;
    if (bid >= TR_TOTAL) {
        const size_t i = ((size_t)(bid - TR_TOTAL) * 256 + threadIdx.x) * 4;
        const size_t per = (size_t)Bn * Dn;
        const int e = (int)(i / per);
        const size_t off = i % per;
        const float4 v = *(const float4*)(p.x[e] + off);
        uint2 w;
        w.x = pack2(v.x, v.y);
        w.y = pack2(v.z, v.w);
        *(uint2*)(g_x16 + i) = w;
        return;
    }
    int s = 0;
#pragma unroll
    for (int i = 0; i < 6; i++) if (bid >= c_segend[i]) s = i + 1;
    const int local = bid - (s ? c_segend[s - 1] : 0);
    const int R = c_R[s], C = c_C[s];
    const int bx = C / 32, bpz = bx * (R / 32);
    const int z = local / bpz;
    const int rem = local - z * bpz;
    const int cb = (rem % bx) * 32, rb = (rem / bx) * 32;

    const float* inp;
    size_t off;
    switch (s) {
        case 0: inp = p.W_task;  off = WT_TASK; break;
        case 1: inp = p.W_b2;    off = WT_B2;   break;
        case 2: inp = p.W_b3;    off = WT_B3;   break;
        case 3: inp = p.Wo_task; off = WOT;     break;
        case 4: inp = p.Wo_b2;   off = WOT + (size_t)8  * 256 * 2048; break;
        default:inp = p.Wo_b3;   off = WOT + (size_t)12 * 256 * 2048; break;
    }
    const float* inz = inp + (size_t)z * R * C;
    __half* outz = g_wt + off + (size_t)z * R * C;

    __shared__ float tile[32][33];
    const int tx = threadIdx.x & 31, ty = threadIdx.x >> 5;
#pragma unroll
    for (int i = ty; i < 32; i += 8)
        tile[i][tx] = inz[(size_t)(rb + i) * C + cb + tx];
    __syncthreads();
#pragma unroll
    for (int i = ty; i < 32; i += 8)
        outz[(size_t)(cb + i) * R + rb + tx] = __float2half_rn(tile[tx][i]);
}

// ===================== Kernel 1: hidden = relu(X_e @ W_e + b_e) =====================
// grid (Hn/128, Bn/128, 18), 256 threads; CTA 128x128x64, warp 64x32 (2x4), occ 2.
// K-chunk 64: double compute per sync/wait → higher tensor duty cycle.
__global__ __launch_bounds__(256, 2) void k_hidden_mma(P p) {
    extern __shared__ __half sm[];
    __half* As[2] = { sm,            sm + HBUF };
    __half* Bs[2] = { sm + 2 * HBUF, sm + 3 * HBUF };

    const int tid = threadIdx.x, wid = tid >> 5, lane = tid & 31;
    const int warp_m = wid >> 2, warp_n = wid & 3;
    const int g = lane >> 2, t = lane & 3;
    const int e = blockIdx.z;
    const int row0 = blockIdx.y * 128, n0 = blockIdx.x * 128;

    const __half *xp0, *xp1 = nullptr, *xp2 = nullptr;
    const float* bias;
    const __half* wt; int K; float* dst32 = nullptr;
    if (e < 8) {
        K = 256; xp0 = g_x16 + (size_t)e * Bn * Dn;
        wt = g_wt + WT_TASK + (size_t)e * Hn * 256;
        bias = p.b_task + e * Hn;
    } else if (e < 12) {
        const int q = e - 8;
        K = 512;
        xp0 = g_x16 + (size_t)2 * Bn * Dn; xp1 = g_x16 + (size_t)3 * Bn * Dn;
        wt = g_wt + WT_B2 + (size_t)q * Hn * 512;
        bias = p.b_b2 + q * Hn;
        dst32 = p.out + SE2_OFF + (size_t)q * BH;
    } else {
        const int q = e - 12;
        K = 768;
        xp0 = g_x16 + (size_t)5 * Bn * Dn; xp1 = g_x16 + (size_t)6 * Bn * Dn;
        xp2 = g_x16 + (size_t)7 * Bn * Dn;
        wt = g_wt + WT_B3 + (size_t)q * Hn * 768;
        bias = p.b_b3 + q * Hn;
        dst32 = p.out + SE3_OFF + (size_t)q * BH;
    }
    __half* dst16 = g_h16 + (size_t)e * BH;

    float acc[4][4][4];
#pragma unroll
    for (int m = 0; m < 4; m++)
#pragma unroll
        for (int n = 0; n < 4; n++)
#pragma unroll
            for (int r = 0; r < 4; r++) acc[m][n][r] = 0.f;

    // Staging: 128 rows x 8 col-groups (8 halves each) = 1024 items / 256 thr = 4 its
    auto CPA = [&](int kc, int s) {
        const int kcol = kc * 64;
        const int part = kcol >> 8, kloc = kcol & 255;   // chunk of 64 never straddles a 256 part
        const __half* xa = (part == 0) ? xp0 : ((part == 1) ? xp1 : xp2);
        const uint32_t ab = smem_u32(As[s]);
#pragma unroll
        for (int it = 0; it < 4; it++) {
            const int item = tid + it * 256;
            const int r = item >> 3, cg = item & 7;
            CP_ASYNC16(ab + (r * HTST + cg * 8) * 2, xa + (size_t)(row0 + r) * Dn + kloc + cg * 8);
        }
    };
    auto CPB = [&](int kc, int s) {
        const int kcol = kc * 64;
        const uint32_t bb = smem_u32(Bs[s]);
#pragma unroll
        for (int it = 0; it < 4; it++) {
            const int item = tid + it * 256;
            const int r = item >> 3, cg = item & 7;
            CP_ASYNC16(bb + (r * HTST + cg * 8) * 2, wt + (size_t)(n0 + r) * K + kcol + cg * 8);
        }
    };
    auto COMPUTE = [&](int s) {
        const uint32_t ab = smem_u32(As[s]);
        const uint32_t bb = smem_u32(Bs[s]);
#pragma unroll
        for (int kt = 0; kt < 4; kt++) {
            uint32_t af[4][4], bf[4][2];
#pragma unroll
            for (int m = 0; m < 4; m++) {
                const uint32_t addr = ab + (((warp_m * 64 + m * 16 + (lane & 15)) * HTST)
                                            + kt * 16 + (lane >> 4) * 8) * 2;
                LDSM4(af[m][0], af[m][1], af[m][2], af[m][3], addr);
            }
#pragma unroll
            for (int nb = 0; nb < 2; nb++) {
                uint32_t r0, r1, r2, r3;
                const uint32_t addr = bb + (((warp_n * 32 + nb * 16 + (lane & 7) + ((lane >> 3) & 1) * 8) * HTST)
                                            + kt * 16 + (lane >> 4) * 8) * 2;
                LDSM4(r0, r1, r2, r3, addr);
                bf[nb * 2][0] = r0;     bf[nb * 2][1] = r2;
                bf[nb * 2 + 1][0] = r1; bf[nb * 2 + 1][1] = r3;
            }
#pragma unroll
            for (int m = 0; m < 4; m++)
#pragma unroll
                for (int n = 0; n < 4; n++) MMA16(acc[m][n], af[m], bf[n]);
        }
    };

    const int KC = K / 64;
    CPA(0, 0); CPB(0, 0); CP_COMMIT();
    CP_WAIT0();
    __syncthreads();
    for (int kc = 0; kc < KC; kc++) {
        const int s = kc & 1;
        const bool more = (kc + 1 < KC);
        if (more) { CPA(kc + 1, s ^ 1); CPB(kc + 1, s ^ 1); CP_COMMIT(); }
        COMPUTE(s);
        if (more) { CP_WAIT0(); __syncthreads(); }
    }

#pragma unroll
    for (int m = 0; m < 4; m++) {
        const int row = row0 + warp_m * 64 + m * 16 + g;
#pragma unroll
        for (int n = 0; n < 4; n++) {
            const int col = n0 + warp_n * 32 + n * 8 + 2 * t;
            const float b0 = bias[col], b1 = bias[col + 1];
            float v0 = fmaxf(acc[m][n][0] + b0, 0.f);
            float v1 = fmaxf(acc[m][n][1] + b1, 0.f);
            float v2 = fmaxf(acc[m][n][2] + b0, 0.f);
            float v3 = fmaxf(acc[m][n][3] + b1, 0.f);
            *(uint32_t*)(dst16 + (size_t)row * Hn + col) = pack2(v0, v1);
            *(uint32_t*)(dst16 + (size_t)(row + 8) * Hn + col) = pack2(v2, v3);
            if (dst32) {
                *(float2*)(dst32 + (size_t)row * Hn + col) = make_float2(v0, v1);
                *(float2*)(dst32 + (size_t)(row + 8) * Hn + col) = make_float2(v2, v3);
            }
        }
    }
}

// ===================== Kernel 2: gates — one warp per (expert,row) =====================
__global__ __launch_bounds__(256) void k_gate(P p) {
    const int gw = blockIdx.x * 8 + (threadIdx.x >> 5);
    const int lane = threadIdx.x & 31;
    const int e = gw >> 12, row = gw & (Bn - 1);

    float s = 0.f;
    float bg;
    if (e < 8) {
        const float* src = p.x[e] + (size_t)row * Dn;
        const float* wg = p.Wg_task + e * Dn;
        bg = p.bg_task[e];
        for (int i = lane * 4; i < Dn; i += 128) {
            const float4 v = *(const float4*)(src + i);
            const float4 w = *(const float4*)(wg + i);
            s += v.x * w.x + v.y * w.y + v.z * w.z + v.w * w.w;
        }
    } else {
        const __half* src = g_h16 + (size_t)e * BH + (size_t)row * Hn;
        const float* wg;
        if (e < 12) { wg = p.Wg_b2 + (e - 8) * Hn;  bg = p.bg_b2[e - 8]; }
        else        { wg = p.Wg_b3 + (e - 12) * Hn; bg = p.bg_b3[e - 12]; }
        for (int i = lane * 8; i < Hn; i += 256) {
            const uint4 hv = *(const uint4*)(src + i);
            const __half2* hp = (const __half2*)&hv;
            const float4 w0 = *(const float4*)(wg + i);
            const float4 w1 = *(const float4*)(wg + i + 4);
            float2 f;
            f = __half22float2(hp[0]); s += f.x * w0.x + f.y * w0.y;
            f = __half22float2(hp[1]); s += f.x * w0.z + f.y * w0.w;
            f = __half22float2(hp[2]); s += f.x * w1.x + f.y * w1.y;
            f = __half22float2(hp[3]); s += f.x * w1.z + f.y * w1.w;
        }
    }
#pragma unroll
    for (int o = 16; o > 0; o >>= 1) s += __shfl_xor_sync(0xFFFFFFFFu, s, o);
    if (lane == 0)
        g_gate[e * Bn + row] = 1.f / (1.f + expf(-(s + bg)));
}

// ===================== Kernel 3: task_out, routed accumulation =====================
// grid (On/128, Bn/128, 8), 256 threads; CTA 128x128x32, warp 64x32 (2x4), occ 2.
__global__ __launch_bounds__(256, 2) void k_out_mma(P p) {
    extern __shared__ __half sm[];
    __half* As[2] = { sm,           sm + BUF };
    __half* Bs[2] = { sm + 2 * BUF, sm + 3 * BUF };
    __shared__ float gs[4][128];
    __shared__ float bsum[128];

    const int tid = threadIdx.x, wid = tid >> 5, lane = tid & 31;
    const int warp_m = wid >> 2, warp_n = wid & 3;
    const int g = lane >> 2, t = lane & 3;
    const int tk = c_order[blockIdx.z];
    const int row0 = blockIdx.y * 128, n0 = blockIdx.x * 128;
    const int nc = c_cnt[tk];

    const __half* hid[4]; const __half* wb[4];
    for (int ci = 0; ci < nc; ci++) {
        const int e = c_lst[tk][ci];
        hid[ci] = g_h16 + (size_t)e * BH;
        wb[ci] = g_wt + WOT + (size_t)e * On * Hn;
    }
    {
        float s = 0.f;
        for (int ci = 0; ci < nc; ci++) {
            const int e = c_lst[tk][ci];
            if (tid < 128) gs[ci][tid] = g_gate[e * Bn + row0 + tid];
            const float* bo = (e < 8) ? (p.bo_task + e * On)
                             : (e < 12) ? (p.bo_b2 + (e - 8) * On)
                                        : (p.bo_b3 + (e - 12) * On);
            if (tid < 128) s += bo[n0 + tid];
        }
        if (tid < 128) bsum[tid] = s;
    }
    __syncthreads();

    float acc[4][4][4];
#pragma unroll
    for (int m = 0; m < 4; m++)
#pragma unroll
        for (int n = 0; n < 4; n++)
#pragma unroll
            for (int r = 0; r < 4; r++) acc[m][n][r] = 0.f;

    const int arow = tid >> 1, acg = (tid & 1) * 2;
    uint4 pa[2];
    auto LDGA = [&](int kc) {
        const int ci = kc >> 6, kcol = (kc & 63) * 32;
        const __half* rp = hid[ci] + (size_t)(row0 + arow) * Hn + kcol;
#pragma unroll
        for (int i = 0; i < 2; i++)
            pa[i] = *(const uint4*)(rp + (acg + i) * 8);
    };
    auto STSA = [&](int kc, int s) {
        const int ci = kc >> 6;
        const float gv = gs[ci][arow];
        __half* ab = As[s];
#pragma unroll
        for (int i = 0; i < 2; i++) {
            const __half2* hp = (const __half2*)&pa[i];
            uint4 w;
            uint32_t* wp = (uint32_t*)&w;
#pragma unroll
            for (int j = 0; j < 4; j++) {
                float2 f = __half22float2(hp[j]);
                wp[j] = pack2(f.x * gv, f.y * gv);
            }
            *(uint4*)(ab + arow * TST + (acg + i) * 8) = w;
        }
    };
    auto CPB = [&](int kc, int s) {
        const int ci = kc >> 6, kcol = (kc & 63) * 32;
        const uint32_t bb = smem_u32(Bs[s]);
#pragma unroll
        for (int it = 0; it < 2; it++) {
            const int item = tid + it * 256;
            const int r = item >> 2, cg = item & 3;
            CP_ASYNC16(bb + (r * TST + cg * 8) * 2, wb[ci] + (size_t)(n0 + r) * Hn + kcol + cg * 8);
        }
    };
    auto COMPUTE = [&](int s) {
        const uint32_t ab = smem_u32(As[s]);
        const uint32_t bb = smem_u32(Bs[s]);
#pragma unroll
        for (int kt = 0; kt < 2; kt++) {
            uint32_t af[4][4], bf[4][2];
#pragma unroll
            for (int m = 0; m < 4; m++) {
                const uint32_t addr = ab + (((warp_m * 64 + m * 16 + (lane & 15)) * TST)
                                            + kt * 16 + (lane >> 4) * 8) * 2;
                LDSM4(af[m][0], af[m][1], af[m][2], af[m][3], addr);
            }
#pragma unroll
            for (int nb = 0; nb < 2; nb++) {
                uint32_t r0, r1, r2, r3;
                const uint32_t addr = bb + (((warp_n * 32 + nb * 16 + (lane & 7) + ((lane >> 3) & 1) * 8) * TST)
                                            + kt * 16 + (lane >> 4) * 8) * 2;
                LDSM4(r0, r1, r2, r3, addr);
                bf[nb * 2][0] = r0;     bf[nb * 2][1] = r2;
                bf[nb * 2 + 1][0] = r1; bf[nb * 2 + 1][1] = r3;
            }
#pragma unroll
            for (int m = 0; m < 4; m++)
#pragma unroll
                for (int n = 0; n < 4; n++) MMA16(acc[m][n], af[m], bf[n]);
        }
    };

    const int KC = nc * 64;
    LDGA(0); CPB(0, 0); CP_COMMIT(); STSA(0, 0);
    CP_WAIT0();
    __syncthreads();
    for (int kc = 0; kc < KC; kc++) {
        const int s = kc & 1;
        const bool more = (kc + 1 < KC);
        if (more) { LDGA(kc + 1); CPB(kc + 1, s ^ 1); CP_COMMIT(); }
        COMPUTE(s);
        if (more) { STSA(kc + 1, s ^ 1); CP_WAIT0(); __syncthreads(); }
    }

    float* outt = p.out + (size_t)tk * Bn * On;
#pragma unroll
    for (int m = 0; m < 4; m++) {
        const int row = row0 + warp_m * 64 + m * 16 + g;
#pragma unroll
        for (int n = 0; n < 4; n++) {
            const int cl = warp_n * 32 + n * 8 + 2 * t;
            const float b0 = bsum[cl], b1 = bsum[cl + 1];
            float2 v;
            v.x = acc[m][n][0] + b0;
            v.y = acc[m][n][1] + b1;
            *(float2*)(outt + (size_t)row * On + n0 + cl) = v;
            v.x = acc[m][n][2] + b0;
            v.y = acc[m][n][3] + b1;
            *(float2*)(outt + (size_t)(row + 8) * On + n0 + cl) = v;
        }
    }
}

// ===================== Host launch =====================
extern "C" void kernel_launch(void* const* d_in, const int* in_sizes, int n_in,
                              void* d_out, int out_size) {
    P p;
    for (int i = 0; i < 8; i++) p.x[i] = (const float*)d_in[i];
    p.W_task  = (const float*)d_in[8];
    p.b_task  = (const float*)d_in[9];
    p.Wg_task = (const float*)d_in[10];
    p.bg_task = (const float*)d_in[11];
    p.Wo_task = (const float*)d_in[12];
    p.bo_task = (const float*)d_in[13];
    p.W_b2    = (const float*)d_in[14];
    p.b_b2    = (const float*)d_in[15];
    p.Wg_b2   = (const float*)d_in[16];
    p.bg_b2   = (const float*)d_in[17];
    p.Wo_b2   = (const float*)d_in[18];
    p.bo_b2   = (const float*)d_in[19];
    p.W_b3    = (const float*)d_in[20];
    p.b_b3    = (const float*)d_in[21];
    p.Wg_b3   = (const float*)d_in[22];
    p.bg_b3   = (const float*)d_in[23];
    p.Wo_b3   = (const float*)d_in[24];
    p.bo_b3   = (const float*)d_in[25];
    p.out = (float*)d_out;

    const int smh = 4 * HBUF * 2;  // 73728 B (K-chunk 64, 2-stage, occ 2)
    const int smo = 4 * BUF * 2;   // 40960 B
    cudaFuncSetAttribute(k_hidden_mma, cudaFuncAttributeMaxDynamicSharedMemorySize, smh);
    cudaFuncSetAttribute(k_out_mma,    cudaFuncAttributeMaxDynamicSharedMemorySize, smo);

    k_prep<<<TR_TOTAL + X16_BLOCKS, 256>>>(p);
    k_hidden_mma<<<dim3(Hn / 128, Bn / 128, 18), 256, smh>>>(p);
    k_gate<<<dim3(18 * Bn / 8), 256>>>(p);
    k_out_mma<<<dim3(On / 128, Bn / 128, 8), 256, smo>>>(p);
}